// round 7
// baseline (speedup 1.0000x reference)
#include <cuda_runtime.h>
#include <cuda_bf16.h>
#include <cstdint>

// ---------------------------------------------------------------------------
// PlanStructuredNetwork via mma.sync bf16 (fp32 acc), bf16x3 split.
// R5: L2 weight-stationary in registers (A=W2 frags resident, B=acts),
//     L2 output transposed [out][row] -> L3 A via ldmatrix.x4.trans,
//     gather of next tile hidden under L3 (warp split).
//   Leaf:  (B*1024, 32) -> 128 -> 128 -> 32
//   Join x10: (B*n, 96) -> 128 -> 128 -> 32,  n = 512..1
// ---------------------------------------------------------------------------

#define NB    2048
#define NLEAF 1024
#define FD    32
#define HD    128
#define OD    32

#define TILE_R  64
#define THREADS 512

__device__ float g_bufA[(size_t)NB * NLEAF * OD];        // 268 MB
__device__ float g_bufB[(size_t)NB * (NLEAF / 2) * OD];  // 134 MB

// --- smem byte offsets ---
#define AA_HI   0           // X [row][k], stride 208
#define AA_LO   17408
#define AB_HI   34816       // H [row][k], stride 272
#define AB_LO   52224
#define W1T_HI  69632       // [128][104] bf16
#define W1T_LO  96256
#define W2T_HI  122880      // staging only; dead after resident preload
#define W2T_LO  157696
#define W3T_HI  192512      // [32][136] bf16
#define W3T_LO  201216
#define B1OFF   209920
#define B2OFF   210432
#define B3OFF   210944
#define SMEM_TOTAL 211072

// AC = H2 transposed [out 128][row 64], stride 144 B; overlays dead W2 staging
#define AC_HI   122880      // 128*144 = 18432
#define AC_LO   141312
#define ACST    144

#define AST_IN  208
#define AST_H   272
#define W1ST    208
#define W2ST    272
#define W3ST    272

// ---------------------------------------------------------------------------
__device__ __forceinline__ uint32_t smem_u32(const void* p) {
    uint32_t a;
    asm("{ .reg .u64 t; cvta.to.shared.u64 t, %1; cvt.u32.u64 %0, t; }"
        : "=r"(a) : "l"(p));
    return a;
}

#define LDSM_X4(r0, r1, r2, r3, addr)                                          \
    asm volatile("ldmatrix.sync.aligned.m8n8.x4.shared.b16 {%0,%1,%2,%3}, [%4];" \
                 : "=r"(r0), "=r"(r1), "=r"(r2), "=r"(r3) : "r"(addr))

#define LDSM_X4_T(r0, r1, r2, r3, addr)                                        \
    asm volatile("ldmatrix.sync.aligned.m8n8.x4.trans.shared.b16 {%0,%1,%2,%3}, [%4];" \
                 : "=r"(r0), "=r"(r1), "=r"(r2), "=r"(r3) : "r"(addr))

#define LDSM_X2(r0, r1, addr)                                                  \
    asm volatile("ldmatrix.sync.aligned.m8n8.x2.shared.b16 {%0,%1}, [%2];"     \
                 : "=r"(r0), "=r"(r1) : "r"(addr))

#define MMA_BF16(c, a0, a1, a2, a3, b0, b1)                                    \
    asm volatile("mma.sync.aligned.m16n8k16.row.col.f32.bf16.bf16.f32 "        \
                 "{%0,%1,%2,%3}, {%4,%5,%6,%7}, {%8,%9}, {%0,%1,%2,%3};"       \
                 : "+f"((c)[0]), "+f"((c)[1]), "+f"((c)[2]), "+f"((c)[3])      \
                 : "r"(a0), "r"(a1), "r"(a2), "r"(a3), "r"(b0), "r"(b1))

__device__ __forceinline__ void split2(float v0, float v1, uint32_t& hi, uint32_t& lo) {
    __nv_bfloat16 h0 = __float2bfloat16(v0);
    __nv_bfloat16 h1 = __float2bfloat16(v1);
    float r0 = v0 - __bfloat162float(h0);
    float r1 = v1 - __bfloat162float(h1);
    __nv_bfloat16 l0 = __float2bfloat16(r0);
    __nv_bfloat16 l1 = __float2bfloat16(r1);
    hi = (uint32_t)__bfloat16_as_ushort(h0) | ((uint32_t)__bfloat16_as_ushort(h1) << 16);
    lo = (uint32_t)__bfloat16_as_ushort(l0) | ((uint32_t)__bfloat16_as_ushort(l1) << 16);
}

// ---------------------------------------------------------------------------
// L1 GEMM (unswapped, as proven): warp = 16 rows x 32 cols, x4 loads.
// ---------------------------------------------------------------------------
template <int NT2, int NK>
__device__ __forceinline__ void gemm3_x4(uint32_t sb,
                                         uint32_t aHiOff, uint32_t aLoOff, int astB,
                                         uint32_t bHiOff, uint32_t bLoOff, int bstB,
                                         int colBase, int lane, int wm,
                                         float c[][4]) {
#pragma unroll
    for (int j = 0; j < 2 * NT2; j++)
#pragma unroll
        for (int q = 0; q < 4; q++) c[j][q] = 0.f;

    const int aRow = wm * 16 + (lane & 15);
    const uint32_t aKb = (uint32_t)(lane >> 4) * 16;
    const uint32_t aHi = sb + aHiOff + (uint32_t)aRow * astB + aKb;
    const uint32_t aLo = sb + aLoOff + (uint32_t)aRow * astB + aKb;

    const int nLoc = (lane & 7) + ((lane >> 4) << 3);
    const uint32_t bKb = (uint32_t)((lane >> 3) & 1) * 16;
    const uint32_t bHi = sb + bHiOff + (uint32_t)(colBase + nLoc) * bstB + bKb;
    const uint32_t bLo = sb + bLoOff + (uint32_t)(colBase + nLoc) * bstB + bKb;

#pragma unroll
    for (int k = 0; k < NK; k++) {
        uint32_t ah0, ah1, ah2, ah3, al0, al1, al2, al3;
        LDSM_X4(ah0, ah1, ah2, ah3, aHi + k * 32);
        LDSM_X4(al0, al1, al2, al3, aLo + k * 32);
#pragma unroll
        for (int j = 0; j < NT2; j++) {
            uint32_t bh0, bh1, bh2, bh3, bl0, bl1, bl2, bl3;
            LDSM_X4(bh0, bh1, bh2, bh3, bHi + j * 16 * bstB + k * 32);
            LDSM_X4(bl0, bl1, bl2, bl3, bLo + j * 16 * bstB + k * 32);
            MMA_BF16(c[2 * j],     ah0, ah1, ah2, ah3, bh0, bh1);
            MMA_BF16(c[2 * j + 1], ah0, ah1, ah2, ah3, bh2, bh3);
            MMA_BF16(c[2 * j],     ah0, ah1, ah2, ah3, bl0, bl1);
            MMA_BF16(c[2 * j + 1], ah0, ah1, ah2, ah3, bl2, bl3);
            MMA_BF16(c[2 * j],     al0, al1, al2, al3, bh0, bh1);
            MMA_BF16(c[2 * j + 1], al0, al1, al2, al3, bh2, bh3);
        }
    }
}

// L1 epilogue: D[m=row][n=col 32] -> AB [row][k] paired 4B stores.
__device__ __forceinline__ void epi128(char* smem, float c[][4],
                                       uint32_t biasOff, uint32_t hiOff, uint32_t loOff,
                                       int lane, int wm, int colBase) {
    int r0 = wm * 16 + (lane >> 2);
#pragma unroll
    for (int t = 0; t < 4; t++) {
        int n0 = colBase + t * 8 + (lane & 3) * 2;
        float2 bb = *(const float2*)(smem + biasOff + n0 * 4);
        {
            float v0 = fmaxf(c[t][0] + bb.x, 0.f);
            float v1 = fmaxf(c[t][1] + bb.y, 0.f);
            uint32_t hi, lo;
            split2(v0, v1, hi, lo);
            uint32_t o = (uint32_t)r0 * AST_H + (uint32_t)n0 * 2;
            *(uint32_t*)(smem + hiOff + o) = hi;
            *(uint32_t*)(smem + loOff + o) = lo;
        }
        {
            float v0 = fmaxf(c[t][2] + bb.x, 0.f);
            float v1 = fmaxf(c[t][3] + bb.y, 0.f);
            uint32_t hi, lo;
            split2(v0, v1, hi, lo);
            uint32_t o = (uint32_t)(r0 + 8) * AST_H + (uint32_t)n0 * 2;
            *(uint32_t*)(smem + hiOff + o) = hi;
            *(uint32_t*)(smem + loOff + o) = lo;
        }
    }
}

// ---------------------------------------------------------------------------
// Gather: input tile -> AA [row][k] hi/lo. tg/nthr select thread subset.
// ---------------------------------------------------------------------------
template <int MODE>
__device__ __forceinline__ void do_gather(char* smem,
                                          const float* __restrict__ in,
                                          const float* __restrict__ prev,
                                          int row0, int logn, int off,
                                          int tg, int nthr) {
    if (MODE == 0) {
        const float2* src = (const float2*)(in + (size_t)row0 * FD);
        for (int i = tg; i < TILE_R * 16; i += nthr) {
            int r = i >> 4, cp = i & 15;
            float2 v = src[i];
            uint32_t hi, lo;
            split2(v.x, v.y, hi, lo);
            uint32_t o = (uint32_t)r * AST_IN + (uint32_t)cp * 4;
            *(uint32_t*)(smem + AA_HI + o) = hi;
            *(uint32_t*)(smem + AA_LO + o) = lo;
        }
    } else {
        const int n = 1 << logn;
        for (int i = tg; i < TILE_R * 48; i += nthr) {
            int r = i / 48, cp = i - r * 48;
            int gr = row0 + r;
            int b = gr >> logn, ii = gr & (n - 1);
            float2 v;
            if (cp < 16)
                v = *(const float2*)(in + (((size_t)b * (NLEAF - 1) + off + ii) << 5) + cp * 2);
            else
                v = *(const float2*)(prev + (((size_t)(b << (logn + 1)) + 2 * ii) << 5) + (cp * 2 - 32));
            uint32_t hi, lo;
            split2(v.x, v.y, hi, lo);
            uint32_t o = (uint32_t)r * AST_IN + (uint32_t)cp * 4;
            *(uint32_t*)(smem + AA_HI + o) = hi;
            *(uint32_t*)(smem + AA_LO + o) = lo;
        }
    }
}

// ---------------------------------------------------------------------------
// MODE: 0 = leaf (in -> bufA), 1 = join A->B, 2 = join B->A
// ---------------------------------------------------------------------------
template <int NK1, int MODE>
__global__ void __launch_bounds__(THREADS, 1)
level_kernel(const float* __restrict__ in,
             const float* __restrict__ W1, const float* __restrict__ b1,
             const float* __restrict__ W2, const float* __restrict__ b2,
             const float* __restrict__ W3, const float* __restrict__ b3,
             int logn, int off, int ntiles) {
    extern __shared__ char smem[];
    uint32_t sb = smem_u32(smem);
    const int tid = threadIdx.x;
    const int lane = tid & 31;
    const int wid = tid >> 5;
    const int wm = wid & 3;        // L1/L3: row group (16 rows)
    const int wn = wid >> 2;       // L1: col group (32 cols); L3: out group
    const int wo = wid & 7;        // L2: out group (16 outs)
    const int wr = wid >> 3;       // L2: row group (32 rows)
    const int K1 = NK1 * 16;

    // --- stage weights (transposed [N][K], hi/lo) + biases in smem ---
    for (int i = tid; i < K1 * HD; i += THREADS) {
        int k = i / HD, n = i - k * HD;
        float v = W1[i];
        __nv_bfloat16 h = __float2bfloat16(v);
        __nv_bfloat16 l = __float2bfloat16(v - __bfloat162float(h));
        uint32_t o = (uint32_t)n * W1ST + (uint32_t)k * 2;
        *(__nv_bfloat16*)(smem + W1T_HI + o) = h;
        *(__nv_bfloat16*)(smem + W1T_LO + o) = l;
    }
    for (int i = tid; i < HD * HD; i += THREADS) {
        int k = i / HD, n = i - k * HD;
        float v = W2[i];
        __nv_bfloat16 h = __float2bfloat16(v);
        __nv_bfloat16 l = __float2bfloat16(v - __bfloat162float(h));
        uint32_t o = (uint32_t)n * W2ST + (uint32_t)k * 2;
        *(__nv_bfloat16*)(smem + W2T_HI + o) = h;
        *(__nv_bfloat16*)(smem + W2T_LO + o) = l;
    }
    for (int i = tid; i < HD * OD; i += THREADS) {
        int k = i / OD, n = i - k * OD;
        float v = W3[i];
        __nv_bfloat16 h = __float2bfloat16(v);
        __nv_bfloat16 l = __float2bfloat16(v - __bfloat162float(h));
        uint32_t o = (uint32_t)n * W3ST + (uint32_t)k * 2;
        *(__nv_bfloat16*)(smem + W3T_HI + o) = h;
        *(__nv_bfloat16*)(smem + W3T_LO + o) = l;
    }
    if (tid < HD) {
        ((float*)(smem + B1OFF))[tid] = b1[tid];
        ((float*)(smem + B2OFF))[tid] = b2[tid];
    }
    if (tid < OD) ((float*)(smem + B3OFF))[tid] = b3[tid];
    __syncthreads();

    // --- resident W2 A-fragments: warp wo owns outs [wo*16, wo*16+16) ---
    uint32_t w2h[8][4], w2l[8][4];
    {
        const uint32_t aRow = (uint32_t)(wo * 16 + (lane & 15));
        const uint32_t aKb = (uint32_t)(lane >> 4) * 16;
        const uint32_t aHi = sb + W2T_HI + aRow * W2ST + aKb;
        const uint32_t aLo = sb + W2T_LO + aRow * W2ST + aKb;
#pragma unroll
        for (int k = 0; k < 8; k++) {
            LDSM_X4(w2h[k][0], w2h[k][1], w2h[k][2], w2h[k][3], aHi + k * 32);
            LDSM_X4(w2l[k][0], w2l[k][1], w2l[k][2], w2l[k][3], aLo + k * 32);
        }
    }

    const float* prev = (MODE == 1) ? g_bufA : g_bufB;
    float* dst = (MODE == 0) ? g_bufA : ((MODE == 1) ? g_bufB : g_bufA);
    const int G = gridDim.x;

    // prologue gather (all threads), also covers W2-staging completion barrier
    if (blockIdx.x < ntiles)
        do_gather<MODE>(smem, in, prev, blockIdx.x * TILE_R, logn, off, tid, THREADS);
    __syncthreads();

    for (int t = blockIdx.x; t < ntiles; t += G) {
        const int row0 = t * TILE_R;

        // ---- layer 1 (unswapped): AA[64 x K1] @ W1T -> AB[64 x 128] ----
        {
            float c[4][4];
            gemm3_x4<2, NK1>(sb, AA_HI, AA_LO, AST_IN, W1T_HI, W1T_LO, W1ST,
                             wn * 32, lane, wm, c);
            epi128(smem, c, B1OFF, AB_HI, AB_LO, lane, wm, wn * 32);
        }
        __syncthreads();

        // ---- layer 2 (weight-stationary): D[out16 x row32] per warp ----
        {
            float c[4][4];
#pragma unroll
            for (int j = 0; j < 4; j++)
#pragma unroll
                for (int q = 0; q < 4; q++) c[j][q] = 0.f;

            const int l15 = lane & 15;
            const uint32_t bRow = (uint32_t)(wr * 32 + (l15 & 7));
            const uint32_t bKb = (uint32_t)((l15 >> 3) & 1) * 16;
            const uint32_t bHi = sb + AB_HI + bRow * AST_H + bKb;
            const uint32_t bLo = sb + AB_LO + bRow * AST_H + bKb;

#pragma unroll
            for (int k = 0; k < 8; k++) {
#pragma unroll
                for (int nt = 0; nt < 4; nt++) {
                    uint32_t bh0, bh1, bl0, bl1;
                    LDSM_X2(bh0, bh1, bHi + nt * 8 * AST_H + k * 32);
                    LDSM_X2(bl0, bl1, bLo + nt * 8 * AST_H + k * 32);
                    MMA_BF16(c[nt], w2h[k][0], w2h[k][1], w2h[k][2], w2h[k][3], bh0, bh1);
                    MMA_BF16(c[nt], w2h[k][0], w2h[k][1], w2h[k][2], w2h[k][3], bl0, bl1);
                    MMA_BF16(c[nt], w2l[k][0], w2l[k][1], w2l[k][2], w2l[k][3], bh0, bh1);
                }
            }

            // epi: D[m=out][n=row] -> AC [out][row], pairs along row = 4B
            const int g = lane >> 2, q = lane & 3;
            const int m = wo * 16 + g;
            const float bm = ((const float*)(smem + B2OFF))[m];
            const float bm8 = ((const float*)(smem + B2OFF))[m + 8];
#pragma unroll
            for (int nt = 0; nt < 4; nt++) {
                uint32_t rb = (uint32_t)(wr * 32 + nt * 8 + 2 * q);
                {
                    float v0 = fmaxf(c[nt][0] + bm, 0.f);
                    float v1 = fmaxf(c[nt][1] + bm, 0.f);
                    uint32_t hi, lo;
                    split2(v0, v1, hi, lo);
                    uint32_t o = (uint32_t)m * ACST + rb * 2;
                    *(uint32_t*)(smem + AC_HI + o) = hi;
                    *(uint32_t*)(smem + AC_LO + o) = lo;
                }
                {
                    float v0 = fmaxf(c[nt][2] + bm8, 0.f);
                    float v1 = fmaxf(c[nt][3] + bm8, 0.f);
                    uint32_t hi, lo;
                    split2(v0, v1, hi, lo);
                    uint32_t o = (uint32_t)(m + 8) * ACST + rb * 2;
                    *(uint32_t*)(smem + AC_HI + o) = hi;
                    *(uint32_t*)(smem + AC_LO + o) = lo;
                }
            }
        }
        __syncthreads();

        // ---- layer 3 (warps 0-7) || gather next tile (warps 8-15) ----
        if (tid < 256) {
            // A = H2 from AC [k=out][m=row] via ldmatrix.x4.trans
            float c[2][4];
#pragma unroll
            for (int j = 0; j < 2; j++)
#pragma unroll
                for (int q2 = 0; q2 < 4; q2++) c[j][q2] = 0.f;

            const uint32_t aKrow = (uint32_t)((lane & 7) + ((lane >> 4) & 1) * 8);
            const uint32_t aMb = (uint32_t)(wm * 16 + ((lane >> 3) & 1) * 8) * 2;
            const uint32_t aHi = sb + AC_HI + aKrow * ACST + aMb;
            const uint32_t aLo = sb + AC_LO + aKrow * ACST + aMb;

            const int l15 = lane & 15;
            const uint32_t bKb = (uint32_t)((l15 >> 3) & 1) * 16;
            const uint32_t bHi = sb + W3T_HI + (uint32_t)(wn * 16 + (l15 & 7)) * W3ST + bKb;
            const uint32_t bLo = sb + W3T_LO + (uint32_t)(wn * 16 + (l15 & 7)) * W3ST + bKb;

#pragma unroll
            for (int k = 0; k < 8; k++) {
                uint32_t ah0, ah1, ah2, ah3, al0, al1, al2, al3;
                LDSM_X4_T(ah0, ah1, ah2, ah3, aHi + k * 16 * ACST);
                LDSM_X4_T(al0, al1, al2, al3, aLo + k * 16 * ACST);
#pragma unroll
                for (int j = 0; j < 2; j++) {
                    uint32_t bh0, bh1, bl0, bl1;
                    LDSM_X2(bh0, bh1, bHi + j * 8 * W3ST + k * 32);
                    LDSM_X2(bl0, bl1, bLo + j * 8 * W3ST + k * 32);
                    MMA_BF16(c[j], ah0, ah1, ah2, ah3, bh0, bh1);
                    MMA_BF16(c[j], ah0, ah1, ah2, ah3, bl0, bl1);
                    MMA_BF16(c[j], al0, al1, al2, al3, bh0, bh1);
                }
            }

            int r0 = row0 + wm * 16 + (lane >> 2);
#pragma unroll
            for (int tt = 0; tt < 2; tt++) {
                int n0 = wn * 16 + tt * 8 + (lane & 3) * 2;
                float2 bb = *(const float2*)(smem + B3OFF + n0 * 4);
                float2 v0 = make_float2(c[tt][0] + bb.x, c[tt][1] + bb.y);
                float2 v1 = make_float2(c[tt][2] + bb.x, c[tt][3] + bb.y);
                *(float2*)(dst + (size_t)r0 * OD + n0) = v0;
                *(float2*)(dst + (size_t)(r0 + 8) * OD + n0) = v1;
            }
        } else {
            int tn = t + G;
            if (tn < ntiles)
                do_gather<MODE>(smem, in, prev, tn * TILE_R, logn, off, tid - 256, 256);
        }
        __syncthreads();
    }
}

// ---------------------------------------------------------------------------
__global__ void extract_kernel(float* __restrict__ out) {
    int b = blockIdx.x * blockDim.x + threadIdx.x;
    if (b < NB) out[b] = g_bufA[(size_t)b * OD];
}

// ---------------------------------------------------------------------------
extern "C" void kernel_launch(void* const* d_in, const int* in_sizes, int n_in,
                              void* d_out, int out_size) {
    const float* leaf_feats = (const float*)d_in[0];
    const float* internal   = (const float*)d_in[1];
    const float* sW1 = (const float*)d_in[2];
    const float* sb1 = (const float*)d_in[3];
    const float* sW2 = (const float*)d_in[4];
    const float* sb2 = (const float*)d_in[5];
    const float* sW3 = (const float*)d_in[6];
    const float* sb3 = (const float*)d_in[7];
    const float* jW1 = (const float*)d_in[8];
    const float* jb1 = (const float*)d_in[9];
    const float* jW2 = (const float*)d_in[10];
    const float* jb2 = (const float*)d_in[11];
    const float* jW3 = (const float*)d_in[12];
    const float* jb3 = (const float*)d_in[13];
    float* out = (float*)d_out;

    cudaFuncSetAttribute(level_kernel<2, 0>, cudaFuncAttributeMaxDynamicSharedMemorySize, SMEM_TOTAL);
    cudaFuncSetAttribute(level_kernel<6, 1>, cudaFuncAttributeMaxDynamicSharedMemorySize, SMEM_TOTAL);
    cudaFuncSetAttribute(level_kernel<6, 2>, cudaFuncAttributeMaxDynamicSharedMemorySize, SMEM_TOTAL);

    // Leaf level: K1 = 32, dst = bufA
    {
        int ntiles = (NB * NLEAF) / TILE_R;     // 32768
        int grid = ntiles < 148 ? ntiles : 148;
        level_kernel<2, 0><<<grid, THREADS, SMEM_TOTAL>>>(
            leaf_feats, sW1, sb1, sW2, sb2, sW3, sb3, 0, 0, ntiles);
    }

    // Join levels n = 512..1; alternate A->B / B->A; final lands in bufA
    int off = 0;
    int mode = 1;
    for (int logn = 9; logn >= 0; --logn) {
        int n = 1 << logn;
        int ntiles = (NB * n) / TILE_R;
        int grid = ntiles < 148 ? ntiles : 148;
        if (mode == 1)
            level_kernel<6, 1><<<grid, THREADS, SMEM_TOTAL>>>(
                internal, jW1, jb1, jW2, jb2, jW3, jb3, logn, off, ntiles);
        else
            level_kernel<6, 2><<<grid, THREADS, SMEM_TOTAL>>>(
                internal, jW1, jb1, jW2, jb2, jW3, jb3, logn, off, ntiles);
        off += n;
        mode = (mode == 1) ? 2 : 1;
    }

    extract_kernel<<<(NB + 255) / 256, 256>>>(out);
}